// round 5
// baseline (speedup 1.0000x reference)
#include <cuda_runtime.h>

#define NROWS 262144
#define HC 64
#define KOFF 27

// Intermediate (relu(conv1)) scratch: static device array (no allocations).
__device__ float g_mid[(size_t)NROWS * HC];

__device__ __forceinline__ unsigned long long pack2(float x, float y) {
    unsigned long long r;
    asm("mov.b64 %0, {%1, %2};" : "=l"(r) : "f"(x), "f"(y));
    return r;
}
__device__ __forceinline__ void unpack2(unsigned long long v, float& x, float& y) {
    asm("mov.b64 {%0, %1}, %2;" : "=f"(x), "=f"(y) : "l"(v));
}
// Blackwell packed dual-fp32 FMA (doubles fp32 throughput vs scalar FFMA).
__device__ __forceinline__ void ffma2(unsigned long long& d, unsigned long long a,
                                      unsigned long long b) {
    asm("fma.rn.f32x2 %0, %1, %2, %0;" : "+l"(d) : "l"(a), "l"(b));
}

// One sparse-conv layer over a 64-row tile.
//   out[r][o] = sum_k sum_c feats[nbr[r][k]][c] * W[k][c][o]   (+relu / +residual)
// Block: 128 threads. Thread tile: 4 rows x 8 cols. Tile: 64 rows x 64 cols.
template <bool RELU, bool RESID>
__global__ __launch_bounds__(128)
void spconv64(const float* __restrict__ feats,
              const float* __restrict__ Wmat,
              const int*   __restrict__ nbr,
              const float* __restrict__ resid,
              float*       __restrict__ out)
{
    __shared__ float As[64][68];   // gathered input tile, +4 pad (272B rows stay 16B-aligned)
    __shared__ float Bs[64][68];   // W[k]
    __shared__ int   idxs[64];

    const int tid  = threadIdx.x;
    const int row0 = blockIdx.x * 64;
    const int ty   = tid >> 3;     // 0..15  -> rows 4*ty..4*ty+3
    const int tx   = tid & 7;      // 0..7   -> cols 8*tx..8*tx+7
    const int gr   = tid >> 1;     // 0..63  gather row
    const int gs   = tid & 1;      // half-row segment (32 floats each)

    unsigned long long acc[4][4];  // [row][col-pair], each = 2 packed fp32
    #pragma unroll
    for (int i = 0; i < 4; i++)
        #pragma unroll
        for (int j = 0; j < 4; j++) acc[i][j] = 0ull;

    for (int k = 0; k < KOFF; k++) {
        __syncthreads();  // protect As/Bs/idxs from previous iteration's readers
        if (tid < 64) idxs[tid] = nbr[(size_t)(row0 + tid) * KOFF + k];
        __syncthreads();

        // Gather A tile: 2 threads per row, 8 float4 each.
        {
            const int idx = idxs[gr];
            if (idx < NROWS) {
                const float4* asrc =
                    reinterpret_cast<const float4*>(feats + (size_t)idx * HC + gs * 32);
                #pragma unroll
                for (int q = 0; q < 8; q++)
                    *reinterpret_cast<float4*>(&As[gr][gs * 32 + q * 4]) = asrc[q];
            } else {
                const float4 z = make_float4(0.f, 0.f, 0.f, 0.f);
                #pragma unroll
                for (int q = 0; q < 8; q++)
                    *reinterpret_cast<float4*>(&As[gr][gs * 32 + q * 4]) = z;
            }
            const float4* bsrc = reinterpret_cast<const float4*>(
                Wmat + (size_t)k * HC * HC + gr * HC + gs * 32);
            #pragma unroll
            for (int q = 0; q < 8; q++)
                *reinterpret_cast<float4*>(&Bs[gr][gs * 32 + q * 4]) = bsrc[q];
        }
        __syncthreads();

        // 64x64x64 GEMM accumulate, packed-f32x2 FMAs.
        #pragma unroll 2
        for (int kk = 0; kk < 64; kk += 4) {
            float4 av[4];
            #pragma unroll
            for (int i = 0; i < 4; i++)
                av[i] = *reinterpret_cast<const float4*>(&As[4 * ty + i][kk]);
            #pragma unroll
            for (int q = 0; q < 4; q++) {
                const float4 b0 = *reinterpret_cast<const float4*>(&Bs[kk + q][8 * tx]);
                const float4 b1 = *reinterpret_cast<const float4*>(&Bs[kk + q][8 * tx + 4]);
                unsigned long long bp[4];
                bp[0] = pack2(b0.x, b0.y);
                bp[1] = pack2(b0.z, b0.w);
                bp[2] = pack2(b1.x, b1.y);
                bp[3] = pack2(b1.z, b1.w);
                #pragma unroll
                for (int i = 0; i < 4; i++) {
                    const float a = (q == 0) ? av[i].x
                                  : (q == 1) ? av[i].y
                                  : (q == 2) ? av[i].z
                                             : av[i].w;
                    const unsigned long long ap = pack2(a, a);
                    #pragma unroll
                    for (int j = 0; j < 4; j++) ffma2(acc[i][j], ap, bp[j]);
                }
            }
        }
    }

    // Epilogue: relu (layer 1) or residual add (layer 2), vectorized stores.
    #pragma unroll
    for (int i = 0; i < 4; i++) {
        const int r = row0 + 4 * ty + i;
        float v[8];
        unpack2(acc[i][0], v[0], v[1]);
        unpack2(acc[i][1], v[2], v[3]);
        unpack2(acc[i][2], v[4], v[5]);
        unpack2(acc[i][3], v[6], v[7]);
        if (RELU) {
            #pragma unroll
            for (int j = 0; j < 8; j++) v[j] = fmaxf(v[j], 0.f);
        }
        if (RESID) {
            const float4 r0 =
                *reinterpret_cast<const float4*>(resid + (size_t)r * HC + 8 * tx);
            const float4 r1 =
                *reinterpret_cast<const float4*>(resid + (size_t)r * HC + 8 * tx + 4);
            v[0] += r0.x; v[1] += r0.y; v[2] += r0.z; v[3] += r0.w;
            v[4] += r1.x; v[5] += r1.y; v[6] += r1.z; v[7] += r1.w;
        }
        *reinterpret_cast<float4*>(out + (size_t)r * HC + 8 * tx) =
            make_float4(v[0], v[1], v[2], v[3]);
        *reinterpret_cast<float4*>(out + (size_t)r * HC + 8 * tx + 4) =
            make_float4(v[4], v[5], v[6], v[7]);
    }
}

extern "C" void kernel_launch(void* const* d_in, const int* in_sizes, int n_in,
                              void* d_out, int out_size) {
    const float* x   = (const float*)d_in[0];
    const float* Wa  = (const float*)d_in[1];
    const float* Wb  = (const float*)d_in[2];
    const int*   nbr = (const int*)d_in[3];
    float*       out = (float*)d_out;

    float* mid = nullptr;
    cudaGetSymbolAddress((void**)&mid, g_mid);

    const int nblocks = NROWS / 64;  // 4096
    spconv64<true,  false><<<nblocks, 128>>>(x,   Wa, nbr, nullptr, mid);
    spconv64<false, true ><<<nblocks, 128>>>(mid, Wb, nbr, x,       out);
}

// round 7
// speedup vs baseline: 4.3182x; 4.3182x over previous
#include <cuda_runtime.h>
#include <cuda_bf16.h>
#include <cstdint>

#define NROWS 262144
#define HC 64
#define KOFF 27
#define TILE_M 128
#define NBLK (NROWS / TILE_M)
#define WSZ (KOFF * HC * HC)
#define APITCH 72   // smem row pitch in bf16 elems (144B) -> conflict-free ldmatrix

// ---------------- device scratch (no allocations allowed) ----------------
// Row NROWS is a zero sentinel (zero-initialized, never written) so gathers
// need no bounds check.
__device__ __nv_bfloat16 g_xh[(size_t)(NROWS + 8) * HC];
__device__ __nv_bfloat16 g_xl[(size_t)(NROWS + 8) * HC];
__device__ __nv_bfloat16 g_mh[(size_t)(NROWS + 8) * HC];
__device__ __nv_bfloat16 g_ml[(size_t)(NROWS + 8) * HC];
// transposed split weights: [layer][k][n][c] bf16
__device__ __nv_bfloat16 g_wh[2 * WSZ];
__device__ __nv_bfloat16 g_wl[2 * WSZ];

// ---------------- helpers (baseline PTX only: ldmatrix + mma.sync) -------
__device__ __forceinline__ uint32_t smem_u32(const void* p) {
    uint32_t a;
    asm("{ .reg .u64 t; cvta.to.shared.u64 t, %1; cvt.u32.u64 %0, t; }" : "=r"(a) : "l"(p));
    return a;
}
__device__ __forceinline__ void ldm4(uint32_t* r, uint32_t addr) {
    asm volatile("ldmatrix.sync.aligned.m8n8.x4.shared.b16 {%0,%1,%2,%3}, [%4];"
                 : "=r"(r[0]), "=r"(r[1]), "=r"(r[2]), "=r"(r[3]) : "r"(addr));
}
__device__ __forceinline__ void mma16816(float* c, const uint32_t* a, const uint32_t* b) {
    asm volatile("mma.sync.aligned.m16n8k16.row.col.f32.bf16.bf16.f32 "
                 "{%0,%1,%2,%3}, {%4,%5,%6,%7}, {%8,%9}, {%0,%1,%2,%3};"
                 : "+f"(c[0]), "+f"(c[1]), "+f"(c[2]), "+f"(c[3])
                 : "r"(a[0]), "r"(a[1]), "r"(a[2]), "r"(a[3]), "r"(b[0]), "r"(b[1]));
}
__device__ __forceinline__ void split1(float v, __nv_bfloat16& h, __nv_bfloat16& l) {
    h = __float2bfloat16(v);
    l = __float2bfloat16(v - __bfloat162float(h));
}
__device__ __forceinline__ uint32_t pk(__nv_bfloat16 a, __nv_bfloat16 b) {
    __nv_bfloat162 t; t.x = a; t.y = b;
    return *reinterpret_cast<uint32_t*>(&t);
}

// ---------------- prep kernels ----------------
__global__ __launch_bounds__(256) void prep_x(const float* __restrict__ x) {
    size_t i = (size_t)blockIdx.x * 256 + threadIdx.x;  // float4 index
    const size_t total = (size_t)(NROWS + 1) * (HC / 4);
    if (i >= total) return;
    float4 v = make_float4(0.f, 0.f, 0.f, 0.f);
    if (i < (size_t)NROWS * (HC / 4)) v = reinterpret_cast<const float4*>(x)[i];
    __nv_bfloat16 h0, h1, h2, h3, l0, l1, l2, l3;
    split1(v.x, h0, l0); split1(v.y, h1, l1); split1(v.z, h2, l2); split1(v.w, h3, l3);
    reinterpret_cast<uint2*>(g_xh)[i] = make_uint2(pk(h0, h1), pk(h2, h3));
    reinterpret_cast<uint2*>(g_xl)[i] = make_uint2(pk(l0, l1), pk(l2, l3));
}

__global__ __launch_bounds__(256) void prep_w(const float* __restrict__ Wa,
                                              const float* __restrict__ Wb) {
    int i = blockIdx.x * 256 + threadIdx.x;
    if (i >= 2 * WSZ) return;
    int l = i / WSZ, r = i % WSZ;
    int k = r / (HC * HC), t = r % (HC * HC), n = t / HC, c = t % HC;
    const float* W = l ? Wb : Wa;
    float v = W[k * HC * HC + c * HC + n];  // transpose to [k][n][c]
    __nv_bfloat16 h, lo; split1(v, h, lo);
    g_wh[i] = h; g_wl[i] = lo;
}

// ---------------- main HMMA kernel ----------------
// smem: Ah[128][72] | Al[128][72] | Bh[64][72] | Bl[64][72]  = 55296 bytes
#define SMEM_TOTAL (384 * APITCH * 2)

template <bool FIRST>
__global__ __launch_bounds__(128, 3)
void spconv_hmma(const __nv_bfloat16* __restrict__ fh,
                 const __nv_bfloat16* __restrict__ fl,
                 const __nv_bfloat16* __restrict__ wh,
                 const __nv_bfloat16* __restrict__ wl,
                 const int* __restrict__ nbr,
                 const float* __restrict__ x,
                 __nv_bfloat16* __restrict__ mh,
                 __nv_bfloat16* __restrict__ ml,
                 float* __restrict__ out)
{
    extern __shared__ __nv_bfloat16 sm[];
    __nv_bfloat16* Ah = sm;
    __nv_bfloat16* Al = sm + 128 * APITCH;
    __nv_bfloat16* Bh = sm + 256 * APITCH;
    __nv_bfloat16* Bl = sm + 320 * APITCH;

    const int tid  = threadIdx.x;
    const int wid  = tid >> 5;
    const int lane = tid & 31;
    const int row0 = blockIdx.x * TILE_M;

    const uint32_t sAh = smem_u32(Ah), sAl = smem_u32(Al);
    const uint32_t sBh = smem_u32(Bh), sBl = smem_u32(Bl);

    // ldmatrix lane address decomposition (x4 = 4 8x8 matrices)
    const int lm = lane & 7, lg = lane >> 3;
    const int a_row = wid * 32 + (lg & 1) * 8 + lm;   // + t*16
    const int a_col = (lg >> 1) * 8;                  // + ks*16
    const int b_row = (lg >> 1) * 8 + lm;             // + np*16
    const int b_col = (lg & 1) * 8;                   // + ks*16

    float acc[2][8][4];
    #pragma unroll
    for (int t = 0; t < 2; t++)
        #pragma unroll
        for (int n = 0; n < 8; n++)
            #pragma unroll
            for (int j = 0; j < 4; j++) acc[t][n][j] = 0.f;

    for (int k = 0; k < KOFF; k++) {
        __syncthreads();   // previous iteration's consumers done

        // --- gather A: one thread per row (sentinel row is zeros) ---
        {
            const int nb = __ldg(&nbr[(size_t)(row0 + tid) * KOFF + k]);
            const uint4* srcH = reinterpret_cast<const uint4*>(fh + (size_t)nb * HC);
            const uint4* srcL = reinterpret_cast<const uint4*>(fl + (size_t)nb * HC);
            uint4* dstH = reinterpret_cast<uint4*>(Ah + tid * APITCH);
            uint4* dstL = reinterpret_cast<uint4*>(Al + tid * APITCH);
            #pragma unroll
            for (int q = 0; q < 8; q++) dstH[q] = __ldg(&srcH[q]);
            #pragma unroll
            for (int q = 0; q < 8; q++) dstL[q] = __ldg(&srcL[q]);
        }
        // --- load B = Wt[k] (64 rows x 64, hi+lo), 2 threads per row ---
        {
            const int br = tid >> 1, bhf = tid & 1;
            const size_t so = (size_t)k * HC * HC + br * HC + bhf * 32;
            const uint4* srcH = reinterpret_cast<const uint4*>(wh + so);
            const uint4* srcL = reinterpret_cast<const uint4*>(wl + so);
            uint4* dstH = reinterpret_cast<uint4*>(Bh + br * APITCH + bhf * 32);
            uint4* dstL = reinterpret_cast<uint4*>(Bl + br * APITCH + bhf * 32);
            #pragma unroll
            for (int q = 0; q < 4; q++) dstH[q] = __ldg(&srcH[q]);
            #pragma unroll
            for (int q = 0; q < 4; q++) dstL[q] = __ldg(&srcL[q]);
        }
        __syncthreads();

        // --- 128x64x64, 3 split passes, warp tile m32 x n64 ---
        #pragma unroll
        for (int ks = 0; ks < 4; ks++) {
            uint32_t ahf[2][4], alf[2][4];
            #pragma unroll
            for (int t = 0; t < 2; t++) {
                const uint32_t off =
                    (uint32_t)(((a_row + t * 16) * APITCH + a_col + ks * 16) * 2);
                ldm4(ahf[t], sAh + off);
                ldm4(alf[t], sAl + off);
            }
            #pragma unroll
            for (int np = 0; np < 4; np++) {
                uint32_t bhf[4], blf[4];
                const uint32_t off =
                    (uint32_t)(((b_row + np * 16) * APITCH + b_col + ks * 16) * 2);
                ldm4(bhf, sBh + off);
                ldm4(blf, sBl + off);
                #pragma unroll
                for (int t = 0; t < 2; t++) {
                    #pragma unroll
                    for (int j = 0; j < 2; j++) {
                        float* c = acc[t][2 * np + j];
                        mma16816(c, ahf[t], &bhf[2 * j]);   // Ah*Bh
                        mma16816(c, ahf[t], &blf[2 * j]);   // Ah*Bl
                        mma16816(c, alf[t], &bhf[2 * j]);   // Al*Bh
                    }
                }
            }
        }
    }

    // --- epilogue (register fragments -> global) ---
    const int erow = row0 + wid * 32 + (lane >> 2);
    const int ecol = (lane & 3) * 2;
    #pragma unroll
    for (int t = 0; t < 2; t++) {
        #pragma unroll
        for (int n = 0; n < 8; n++) {
            #pragma unroll
            for (int rr = 0; rr < 2; rr++) {
                const int r = erow + t * 16 + rr * 8;
                const int c = n * 8 + ecol;
                float v0 = acc[t][n][2 * rr];
                float v1 = acc[t][n][2 * rr + 1];
                if (FIRST) {
                    v0 = fmaxf(v0, 0.f);
                    v1 = fmaxf(v1, 0.f);
                    __nv_bfloat16 h0, l0, h1, l1;
                    split1(v0, h0, l0);
                    split1(v1, h1, l1);
                    *reinterpret_cast<uint32_t*>(mh + (size_t)r * HC + c) = pk(h0, h1);
                    *reinterpret_cast<uint32_t*>(ml + (size_t)r * HC + c) = pk(l0, l1);
                } else {
                    const float2 xv =
                        *reinterpret_cast<const float2*>(x + (size_t)r * HC + c);
                    float2 o;
                    o.x = v0 + xv.x;
                    o.y = v1 + xv.y;
                    *reinterpret_cast<float2*>(out + (size_t)r * HC + c) = o;
                }
            }
        }
    }
}

// ---------------- launch ----------------
extern "C" void kernel_launch(void* const* d_in, const int* in_sizes, int n_in,
                              void* d_out, int out_size) {
    const float* x   = (const float*)d_in[0];
    const float* Wa  = (const float*)d_in[1];
    const float* Wb  = (const float*)d_in[2];
    const int*   nbr = (const int*)d_in[3];
    float*       out = (float*)d_out;

    __nv_bfloat16 *xh, *xl, *mh, *ml, *wh, *wl;
    cudaGetSymbolAddress((void**)&xh, g_xh);
    cudaGetSymbolAddress((void**)&xl, g_xl);
    cudaGetSymbolAddress((void**)&mh, g_mh);
    cudaGetSymbolAddress((void**)&ml, g_ml);
    cudaGetSymbolAddress((void**)&wh, g_wh);
    cudaGetSymbolAddress((void**)&wl, g_wl);

    cudaFuncSetAttribute(spconv_hmma<true>,
                         cudaFuncAttributeMaxDynamicSharedMemorySize, SMEM_TOTAL);
    cudaFuncSetAttribute(spconv_hmma<false>,
                         cudaFuncAttributeMaxDynamicSharedMemorySize, SMEM_TOTAL);

    const size_t xtot = (size_t)(NROWS + 1) * (HC / 4);
    prep_x<<<(int)((xtot + 255) / 256), 256>>>(x);
    prep_w<<<(2 * WSZ + 255) / 256, 256>>>(Wa, Wb);

    // layer 1: relu(conv(x, Wa)) -> split mid
    spconv_hmma<true><<<NBLK, 128, SMEM_TOTAL>>>(
        xh, xl, wh, wl, nbr, nullptr, mh, ml, nullptr);
    // layer 2: conv(mid, Wb) + x -> out
    spconv_hmma<false><<<NBLK, 128, SMEM_TOTAL>>>(
        mh, ml, wh + WSZ, wl + WSZ, nbr, x, nullptr, nullptr, out);
}